// round 12
// baseline (speedup 1.0000x reference)
#include <cuda_runtime.h>
#include <math.h>
#include <stdint.h>

// Problem constants
#define BATCH 2
#define SEQ   2048
#define HDIM  1024
#define NHEAD 16
#define HEADD 64
#define MROWS (BATCH * SEQ)   // 4096
#define GK    1024
#define GN    1024

#define LOG2E 1.4426950408889634f

// Scratch buffers (device globals: allocation-free, graph-capturable)
__device__ float g_q[MROWS * HDIM];
__device__ float g_k[MROWS * HDIM];
__device__ float g_v[MROWS * HDIM];   // holds V TRANSPOSED: [b][h][d][seq]
__device__ float g_ctx[MROWS * HDIM];

__device__ __forceinline__ uint32_t f2tf32(float f) {
    uint32_t r;
    asm("cvt.rna.tf32.f32 %0, %1;" : "=r"(r) : "f"(f));
    return r;
}
__device__ __forceinline__ float tf32f(float f) {
    return __uint_as_float(f2tf32(f));
}
__device__ __forceinline__ float ex2(float x) {
    float r;
    asm("ex2.approx.f32 %0, %1;" : "=f"(r) : "f"(x));
    return r;
}

__device__ __forceinline__ void mma_tf32(float d[4],
                                         uint32_t a0, uint32_t a1,
                                         uint32_t a2, uint32_t a3,
                                         uint32_t b0, uint32_t b1) {
    asm volatile(
        "mma.sync.aligned.m16n8k8.row.col.f32.tf32.tf32.f32 "
        "{%0,%1,%2,%3}, {%4,%5,%6,%7}, {%8,%9}, {%0,%1,%2,%3};"
        : "+f"(d[0]), "+f"(d[1]), "+f"(d[2]), "+f"(d[3])
        : "r"(a0), "r"(a1), "r"(a2), "r"(a3), "r"(b0), "r"(b1));
}

// ---------------------------------------------------------------------------
// GEMM core (tf32 mma.sync): acc = A[bm:+128] @ W[bn:+128]^T, K=1024.
// Pair-k smem layout [p][128][16] (p-stride 2056 floats), XOR swizzle:
// staging stores AND fragment reads conflict-free; every fragment = LDS.128.
// 256 threads, 8 warps (4M x 2N), warp tile 32x64, reg double-buffer.
// ---------------------------------------------------------------------------
#define PSTR 2056   // floats between p-blocks (2056 mod 32 = 8 -> store CF)

__device__ __forceinline__ void gemm_core(const float* __restrict__ A,
                                          const float* __restrict__ W,
                                          float* As, float* Bs,
                                          float acc[2][8][4],
                                          int bm, int bn)
{
    const int tid  = threadIdx.x;
    const int wid  = tid >> 5;
    const int lane = tid & 31;
    const int g    = lane >> 2;
    const int t    = lane & 3;
    const int xg   = (g >> 1) & 3;
    const int wm   = wid & 3;
    const int wn   = wid >> 2;

    // staging: thread owns row lr, 16-float half h (== p-block h)
    const int lr = tid >> 1;
    const int h  = tid & 1;
    const int xr = (lr >> 1) & 3;
    const float* ag = A + (size_t)(bm + lr) * GK + h * 16;
    const float* wg = W + (size_t)(bn + lr) * GK + h * 16;
    float* asd = As + h * PSTR + lr * 16;
    float* bsd = Bs + h * PSTR + lr * 16;

#pragma unroll
    for (int mi = 0; mi < 2; mi++)
#pragma unroll
        for (int nt = 0; nt < 8; nt++)
#pragma unroll
            for (int x = 0; x < 4; x++) acc[mi][nt][x] = 0.0f;

    float4 sa[4], sb[4];
#pragma unroll
    for (int w = 0; w < 4; w++) {
        sa[w] = *(const float4*)(ag + w * 4);
        sb[w] = *(const float4*)(wg + w * 4);
    }

    const float* pAbase = As + (wm * 32 + g) * 16 + 4 * (t ^ xg);
    const float* pBbase = Bs + (wn * 64 + g) * 16 + 4 * (t ^ xg);

    for (int it = 0; it < GK / 32; ++it) {
        // pair-k permuted store: float4 (f[u], f[u+4], f[8+u], f[12+u])
        {
            float fa[16], fb[16];
#pragma unroll
            for (int w = 0; w < 4; w++) {
                fa[w*4+0] = tf32f(sa[w].x); fa[w*4+1] = tf32f(sa[w].y);
                fa[w*4+2] = tf32f(sa[w].z); fa[w*4+3] = tf32f(sa[w].w);
                fb[w*4+0] = tf32f(sb[w].x); fb[w*4+1] = tf32f(sb[w].y);
                fb[w*4+2] = tf32f(sb[w].z); fb[w*4+3] = tf32f(sb[w].w);
            }
#pragma unroll
            for (int u = 0; u < 4; u++) {
                *(float4*)(asd + 4 * (u ^ xr)) =
                    make_float4(fa[u], fa[u+4], fa[8+u], fa[12+u]);
                *(float4*)(bsd + 4 * (u ^ xr)) =
                    make_float4(fb[u], fb[u+4], fb[8+u], fb[12+u]);
            }
        }
        __syncthreads();

        if (it + 1 < GK / 32) {
            const float* agn = ag + (it + 1) * 32;
            const float* wgn = wg + (it + 1) * 32;
#pragma unroll
            for (int w = 0; w < 4; w++) {
                sa[w] = *(const float4*)(agn + w * 4);
                sb[w] = *(const float4*)(wgn + w * 4);
            }
        }

#pragma unroll
        for (int p = 0; p < 2; p++) {
            uint32_t af[2][2][4];
#pragma unroll
            for (int mi = 0; mi < 2; mi++) {
                float4 lo = *(const float4*)(pAbase + p * PSTR + mi * 256);
                float4 hi = *(const float4*)(pAbase + p * PSTR + mi * 256 + 128);
                af[mi][0][0] = __float_as_uint(lo.x);
                af[mi][0][1] = __float_as_uint(hi.x);
                af[mi][0][2] = __float_as_uint(lo.y);
                af[mi][0][3] = __float_as_uint(hi.y);
                af[mi][1][0] = __float_as_uint(lo.z);
                af[mi][1][1] = __float_as_uint(hi.z);
                af[mi][1][2] = __float_as_uint(lo.w);
                af[mi][1][3] = __float_as_uint(hi.w);
            }
#pragma unroll
            for (int nt = 0; nt < 8; nt++) {
                float4 bb = *(const float4*)(pBbase + p * PSTR + nt * 128);
                uint32_t b0 = __float_as_uint(bb.x), b1 = __float_as_uint(bb.y);
                uint32_t b2 = __float_as_uint(bb.z), b3 = __float_as_uint(bb.w);
                mma_tf32(acc[0][nt], af[0][0][0], af[0][0][1], af[0][0][2], af[0][0][3], b0, b1);
                mma_tf32(acc[1][nt], af[1][0][0], af[1][0][1], af[1][0][2], af[1][0][3], b0, b1);
                mma_tf32(acc[0][nt], af[0][1][0], af[0][1][1], af[0][1][2], af[0][1][3], b2, b3);
                mma_tf32(acc[1][nt], af[1][1][0], af[1][1][1], af[1][1][2], af[1][1][3], b2, b3);
            }
        }
        __syncthreads();
    }
}

// Fused QKV: grid.x in [0,24): sel = x>>3 (0=Q,1=K,2=V), bn = (x&7)*128.
// V epilogue writes transposed per-head layout: vT[(b*1024 + col)*2048 + j].
__global__ __launch_bounds__(256, 2)
void qkv_kernel(const float* __restrict__ hs,
                const float* __restrict__ Wq, const float* __restrict__ bq,
                const float* __restrict__ Wk, const float* __restrict__ bk,
                const float* __restrict__ Wv, const float* __restrict__ bv,
                float* __restrict__ Cq, float* __restrict__ Ck,
                float* __restrict__ CvT)
{
    __shared__ float As[2 * PSTR];
    __shared__ float Bs[2 * PSTR];

    const int sel = blockIdx.x >> 3;
    const int bn  = (blockIdx.x & 7) * 128;
    const int bm  = blockIdx.y * 128;
    const float* W    = (sel == 0) ? Wq : (sel == 1) ? Wk : Wv;
    const float* bias = (sel == 0) ? bq : (sel == 1) ? bk : bv;

    float acc[2][8][4];
    gemm_core(hs, W, As, Bs, acc, bm, bn);

    const int lane = threadIdx.x & 31;
    const int wid  = threadIdx.x >> 5;
    const int g    = lane >> 2;
    const int t    = lane & 3;
    const int wm   = wid & 3;
    const int wn   = wid >> 2;

    if (sel < 2) {
        float* C = (sel == 0) ? Cq : Ck;
#pragma unroll
        for (int mi = 0; mi < 2; mi++) {
            const int row0 = bm + wm * 32 + mi * 16 + g;
#pragma unroll
            for (int nt = 0; nt < 8; nt++) {
                const int col = bn + wn * 64 + nt * 8 + 2 * t;
                const float2 bv2 = *(const float2*)(bias + col);
                float2 o0, o1;
                o0.x = acc[mi][nt][0] + bv2.x; o0.y = acc[mi][nt][1] + bv2.y;
                o1.x = acc[mi][nt][2] + bv2.x; o1.y = acc[mi][nt][3] + bv2.y;
                *(float2*)(C + (size_t)row0 * GN + col)       = o0;
                *(float2*)(C + (size_t)(row0 + 8) * GN + col) = o1;
            }
        }
    } else {
        // transposed store: vT[(b*1024 + col)*2048 + j], j = row & 2047
#pragma unroll
        for (int mi = 0; mi < 2; mi++) {
            const int row0 = bm + wm * 32 + mi * 16 + g;
            const int bidx = row0 >> 11;
            const int j    = row0 & 2047;
#pragma unroll
            for (int nt = 0; nt < 8; nt++) {
                const int col = bn + wn * 64 + nt * 8 + 2 * t;
                const float2 bv2 = *(const float2*)(bias + col);
                float* base0 = CvT + (size_t)(bidx * 1024 + col) * 2048;
                float* base1 = CvT + (size_t)(bidx * 1024 + col + 1) * 2048;
                base0[j]     = acc[mi][nt][0] + bv2.x;
                base1[j]     = acc[mi][nt][1] + bv2.y;
                base0[j + 8] = acc[mi][nt][2] + bv2.x;
                base1[j + 8] = acc[mi][nt][3] + bv2.y;
            }
        }
    }
}

// Plain GEMM (for the output projection)
__global__ __launch_bounds__(256, 2)
void gemm_kernel(const float* __restrict__ A,
                 const float* __restrict__ W,
                 const float* __restrict__ bias,
                 float* __restrict__ C)
{
    __shared__ float As[2 * PSTR];
    __shared__ float Bs[2 * PSTR];

    const int bn = blockIdx.x * 128;
    const int bm = blockIdx.y * 128;

    float acc[2][8][4];
    gemm_core(A, W, As, Bs, acc, bm, bn);

    const int lane = threadIdx.x & 31;
    const int wid  = threadIdx.x >> 5;
    const int g    = lane >> 2;
    const int t    = lane & 3;
    const int wm   = wid & 3;
    const int wn   = wid >> 2;

#pragma unroll
    for (int mi = 0; mi < 2; mi++) {
        const int row0 = bm + wm * 32 + mi * 16 + g;
#pragma unroll
        for (int nt = 0; nt < 8; nt++) {
            const int col = bn + wn * 64 + nt * 8 + 2 * t;
            const float2 bv2 = *(const float2*)(bias + col);
            float2 o0, o1;
            o0.x = acc[mi][nt][0] + bv2.x; o0.y = acc[mi][nt][1] + bv2.y;
            o1.x = acc[mi][nt][2] + bv2.x; o1.y = acc[mi][nt][3] + bv2.y;
            *(float2*)(C + (size_t)row0 * GN + col)       = o0;
            *(float2*)(C + (size_t)(row0 + 8) * GN + col) = o1;
        }
    }
}

// ---------------------------------------------------------------------------
// Tensor-core flash attention (tf32 mma.sync), V pre-transposed in gmem.
// 128 threads / 4 warps, warp owns 32 q-rows; pair-k + XOR swizzle layout.
// ---------------------------------------------------------------------------
#define KSTR 80

__global__ __launch_bounds__(128, 2)
void attn_tc_kernel(const float* __restrict__ Q,
                    const float* __restrict__ Kg,
                    const float* __restrict__ VT,
                    const float* __restrict__ mask,
                    float* __restrict__ ctx)
{
    __shared__ float sm[2 * 64 * KSTR + 64];
    float* Ks  = sm;                 // [64 j][KSTR]  pair-k on d
    float* VsT = sm + 64 * KSTR;     // [64 d][KSTR]  pair-k on j
    float* Qs  = sm;                 // [128 r][KSTR] staging overlay
    float* msk = sm + 2 * 64 * KSTR; // [64] physical j, pre-scaled by LOG2E

    const int tid  = threadIdx.x;
    const int lane = tid & 31;
    const int wid  = tid >> 5;
    const int g    = lane >> 2;
    const int t    = lane & 3;
    const int xg   = (g >> 1) & 3;
    const int bh   = blockIdx.y;
    const int b    = bh >> 4;
    const int h    = bh & 15;
    const int q0   = blockIdx.x * 128;
    const int wq   = wid * 32;

    const float SC = 0.125f * LOG2E;

    const float* Qb  = Q  + (size_t)b * SEQ * HDIM + h * HEADD;
    const float* Kb  = Kg + (size_t)b * SEQ * HDIM + h * HEADD;
    const float* VTb = VT + (size_t)(b * 1024 + h * 64) * 2048;  // rows = d

    // --- Stage Q (pair-k + XOR layout): thread owns row lr = tid ---
    {
        const int lr = tid;
        const int xr = (lr >> 1) & 3;
        const float* src = Qb + (size_t)(q0 + lr) * HDIM;
        float* qrow = &Qs[lr * KSTR];
#pragma unroll
        for (int p = 0; p < 4; p++) {
            float f[16];
#pragma unroll
            for (int w = 0; w < 4; w++) {
                float4 v = *(const float4*)(src + p * 16 + w * 4);
                f[w * 4 + 0] = tf32f(v.x); f[w * 4 + 1] = tf32f(v.y);
                f[w * 4 + 2] = tf32f(v.z); f[w * 4 + 3] = tf32f(v.w);
            }
#pragma unroll
            for (int u = 0; u < 4; u++) {
                float4 d4 = make_float4(f[u], f[u + 4], f[8 + u], f[12 + u]);
                *(float4*)(qrow + p * 16 + 4 * (u ^ xr)) = d4;
            }
        }
    }
    __syncthreads();

    // --- Persistent Q fragments: qf[mi][ks][4] ---
    uint32_t qf[2][8][4];
#pragma unroll
    for (int mi = 0; mi < 2; mi++) {
        const int row = wq + mi * 16 + g;
#pragma unroll
        for (int p = 0; p < 4; p++) {
            float4 lo = *(const float4*)&Qs[row * KSTR + p * 16 + 4 * (t ^ xg)];
            float4 hi = *(const float4*)&Qs[(row + 8) * KSTR + p * 16 + 4 * (t ^ xg)];
            qf[mi][2 * p][0]     = __float_as_uint(lo.x);
            qf[mi][2 * p][1]     = __float_as_uint(hi.x);
            qf[mi][2 * p][2]     = __float_as_uint(lo.y);
            qf[mi][2 * p][3]     = __float_as_uint(hi.y);
            qf[mi][2 * p + 1][0] = __float_as_uint(lo.z);
            qf[mi][2 * p + 1][1] = __float_as_uint(hi.z);
            qf[mi][2 * p + 1][2] = __float_as_uint(lo.w);
            qf[mi][2 * p + 1][3] = __float_as_uint(hi.w);
        }
    }
    __syncthreads();

    float oacc[2][8][4];
#pragma unroll
    for (int mi = 0; mi < 2; mi++)
#pragma unroll
        for (int nt = 0; nt < 8; nt++)
#pragma unroll
            for (int x = 0; x < 4; x++) oacc[mi][nt][x] = 0.0f;
    float lsum[2][2] = {{0.f, 0.f}, {0.f, 0.f}};

    const int src0 = (lane & ~3) | ((lane >> 1) & 1);
    const int src1 = src0 + 2;
    const bool odd = (t & 1);

    // loaders: 128 threads = 64 rows x 2 column-segments of 32
    const int rr  = tid & 63;            // K: j row; V: d row
    const int seg = (tid >> 6) * 32;     // K: d cols; V: j cols
    const int xr2 = (rr >> 1) & 3;

    for (int k0 = 0; k0 < SEQ; k0 += 64) {
        // --- Stage K chunk: rows j, pair-k on d ---
        {
            const float* ksrc = Kb + (size_t)(k0 + rr) * HDIM + seg;
            float* krow = &Ks[rr * KSTR + seg];
#pragma unroll
            for (int pp = 0; pp < 2; pp++) {
                float f[16];
#pragma unroll
                for (int w = 0; w < 4; w++) {
                    float4 v = *(const float4*)(ksrc + pp * 16 + w * 4);
                    f[w * 4 + 0] = tf32f(v.x); f[w * 4 + 1] = tf32f(v.y);
                    f[w * 4 + 2] = tf32f(v.z); f[w * 4 + 3] = tf32f(v.w);
                }
#pragma unroll
                for (int u = 0; u < 4; u++) {
                    float4 d4 = make_float4(f[u], f[u + 4], f[8 + u], f[12 + u]);
                    *(float4*)(krow + pp * 16 + 4 * (u ^ xr2)) = d4;
                }
            }
            // --- Stage V chunk from VT: rows d, pair-k on j (vectorized) ---
            const float* vsrc = VTb + (size_t)rr * 2048 + k0 + seg;
            float* vrow = &VsT[rr * KSTR + seg];
#pragma unroll
            for (int pp = 0; pp < 2; pp++) {
                float f[16];
#pragma unroll
                for (int w = 0; w < 4; w++) {
                    float4 v = *(const float4*)(vsrc + pp * 16 + w * 4);
                    f[w * 4 + 0] = tf32f(v.x); f[w * 4 + 1] = tf32f(v.y);
                    f[w * 4 + 2] = tf32f(v.z); f[w * 4 + 3] = tf32f(v.w);
                }
#pragma unroll
                for (int u = 0; u < 4; u++) {
                    float4 d4 = make_float4(f[u], f[u + 4], f[8 + u], f[12 + u]);
                    *(float4*)(vrow + pp * 16 + 4 * (u ^ xr2)) = d4;
                }
            }
        }
        if (tid < 64) msk[tid] = mask[(size_t)b * SEQ + k0 + tid] * LOG2E;
        __syncthreads();

        // --- S = Q @ K^T ---
        float sacc[2][8][4];
#pragma unroll
        for (int mi = 0; mi < 2; mi++)
#pragma unroll
            for (int nt = 0; nt < 8; nt++)
#pragma unroll
                for (int x = 0; x < 4; x++) sacc[mi][nt][x] = 0.0f;

#pragma unroll
        for (int p = 0; p < 4; p++) {
#pragma unroll
            for (int nt = 0; nt < 8; nt++) {
                float4 bb = *(const float4*)&Ks[(nt * 8 + g) * KSTR + p * 16 + 4 * (t ^ xg)];
                uint32_t b0 = __float_as_uint(bb.x), b1 = __float_as_uint(bb.y);
                uint32_t b2 = __float_as_uint(bb.z), b3 = __float_as_uint(bb.w);
                mma_tf32(sacc[0][nt], qf[0][2*p][0], qf[0][2*p][1], qf[0][2*p][2], qf[0][2*p][3], b0, b1);
                mma_tf32(sacc[1][nt], qf[1][2*p][0], qf[1][2*p][1], qf[1][2*p][2], qf[1][2*p][3], b0, b1);
                mma_tf32(sacc[0][nt], qf[0][2*p+1][0], qf[0][2*p+1][1], qf[0][2*p+1][2], qf[0][2*p+1][3], b2, b3);
                mma_tf32(sacc[1][nt], qf[1][2*p+1][0], qf[1][2*p+1][1], qf[1][2*p+1][2], qf[1][2*p+1][3], b2, b3);
            }
        }

        // --- softmax numerators (single-pass, exp2) + tf32 P in-place ---
#pragma unroll
        for (int mi = 0; mi < 2; mi++)
#pragma unroll
            for (int nt = 0; nt < 8; nt++) {
                float2 mk = *(const float2*)&msk[nt * 8 + 2 * t];
                float e0 = ex2(fmaf(sacc[mi][nt][0], SC, mk.x));
                float e1 = ex2(fmaf(sacc[mi][nt][1], SC, mk.y));
                float e2 = ex2(fmaf(sacc[mi][nt][2], SC, mk.x));
                float e3 = ex2(fmaf(sacc[mi][nt][3], SC, mk.y));
                lsum[mi][0] += e0 + e1;
                lsum[mi][1] += e2 + e3;
                sacc[mi][nt][0] = tf32f(e0); sacc[mi][nt][1] = tf32f(e1);
                sacc[mi][nt][2] = tf32f(e2); sacc[mi][nt][3] = tf32f(e3);
            }

        // --- O += P @ V ---
#pragma unroll
        for (int p = 0; p < 4; p++) {
            uint32_t pf[2][2][4];
#pragma unroll
            for (int mi = 0; mi < 2; mi++)
#pragma unroll
                for (int kk = 0; kk < 2; kk++) {
                    const int ks = 2 * p + kk;
                    float v00 = __shfl_sync(0xffffffffu, sacc[mi][ks][0], src0);
                    float v01 = __shfl_sync(0xffffffffu, sacc[mi][ks][1], src0);
                    float v10 = __shfl_sync(0xffffffffu, sacc[mi][ks][2], src0);
                    float v11 = __shfl_sync(0xffffffffu, sacc[mi][ks][3], src0);
                    float w00 = __shfl_sync(0xffffffffu, sacc[mi][ks][0], src1);
                    float w01 = __shfl_sync(0xffffffffu, sacc[mi][ks][1], src1);
                    float w10 = __shfl_sync(0xffffffffu, sacc[mi][ks][2], src1);
                    float w11 = __shfl_sync(0xffffffffu, sacc[mi][ks][3], src1);
                    pf[mi][kk][0] = __float_as_uint(odd ? v01 : v00);
                    pf[mi][kk][1] = __float_as_uint(odd ? v11 : v10);
                    pf[mi][kk][2] = __float_as_uint(odd ? w01 : w00);
                    pf[mi][kk][3] = __float_as_uint(odd ? w11 : w10);
                }
#pragma unroll
            for (int nt = 0; nt < 8; nt++) {
                float4 bb = *(const float4*)&VsT[(nt * 8 + g) * KSTR + p * 16 + 4 * (t ^ xg)];
                uint32_t b0 = __float_as_uint(bb.x), b1 = __float_as_uint(bb.y);
                uint32_t b2 = __float_as_uint(bb.z), b3 = __float_as_uint(bb.w);
                mma_tf32(oacc[0][nt], pf[0][0][0], pf[0][0][1], pf[0][0][2], pf[0][0][3], b0, b1);
                mma_tf32(oacc[1][nt], pf[1][0][0], pf[1][0][1], pf[1][0][2], pf[1][0][3], b0, b1);
                mma_tf32(oacc[0][nt], pf[0][1][0], pf[0][1][1], pf[0][1][2], pf[0][1][3], b2, b3);
                mma_tf32(oacc[1][nt], pf[1][1][0], pf[1][1][1], pf[1][1][2], pf[1][1][3], b2, b3);
            }
        }
        __syncthreads();
    }

    // --- Final row-sum reduction, normalize, store ---
#pragma unroll
    for (int mi = 0; mi < 2; mi++) {
        lsum[mi][0] += __shfl_xor_sync(0xffffffffu, lsum[mi][0], 1);
        lsum[mi][0] += __shfl_xor_sync(0xffffffffu, lsum[mi][0], 2);
        lsum[mi][1] += __shfl_xor_sync(0xffffffffu, lsum[mi][1], 1);
        lsum[mi][1] += __shfl_xor_sync(0xffffffffu, lsum[mi][1], 2);
        const float inv0 = 1.0f / lsum[mi][0];
        const float inv1 = 1.0f / lsum[mi][1];

        const int row0 = q0 + wq + mi * 16 + g;
        float* c0 = ctx + (size_t)(b * SEQ + row0) * HDIM + h * HEADD + 2 * t;
        float* c1 = ctx + (size_t)(b * SEQ + row0 + 8) * HDIM + h * HEADD + 2 * t;
#pragma unroll
        for (int nt = 0; nt < 8; nt++) {
            float2 o0 = make_float2(oacc[mi][nt][0] * inv0, oacc[mi][nt][1] * inv0);
            float2 o1 = make_float2(oacc[mi][nt][2] * inv1, oacc[mi][nt][3] * inv1);
            *(float2*)(c0 + nt * 8) = o0;
            *(float2*)(c1 + nt * 8) = o1;
        }
    }
}

// ---------------------------------------------------------------------------
// Launch
// ---------------------------------------------------------------------------
extern "C" void kernel_launch(void* const* d_in, const int* in_sizes, int n_in,
                              void* d_out, int out_size)
{
    const float* hs   = (const float*)d_in[0];
    const float* mask = (const float*)d_in[1];
    const float* Wq   = (const float*)d_in[2];
    const float* bq   = (const float*)d_in[3];
    const float* Wk   = (const float*)d_in[4];
    const float* bk   = (const float*)d_in[5];
    const float* Wv   = (const float*)d_in[6];
    const float* bv   = (const float*)d_in[7];
    const float* Wo   = (const float*)d_in[8];
    const float* bo   = (const float*)d_in[9];
    float* out = (float*)d_out;

    float *qp, *kp, *vp, *cp;
    cudaGetSymbolAddress((void**)&qp, g_q);
    cudaGetSymbolAddress((void**)&kp, g_k);
    cudaGetSymbolAddress((void**)&vp, g_v);
    cudaGetSymbolAddress((void**)&cp, g_ctx);

    qkv_kernel<<<dim3(24, 32), dim3(256)>>>(hs, Wq, bq, Wk, bk, Wv, bv,
                                            qp, kp, vp);

    attn_tc_kernel<<<dim3(SEQ / 128, BATCH * NHEAD), dim3(128)>>>(
        qp, kp, vp, mask, cp);

    gemm_kernel<<<dim3(8, 32), dim3(256)>>>(cp, Wo, bo, out);
}

// round 13
// speedup vs baseline: 1.8391x; 1.8391x over previous
#include <cuda_runtime.h>
#include <cuda_fp16.h>
#include <math.h>
#include <stdint.h>

// Problem constants
#define BATCH 2
#define SEQ   2048
#define HDIM  1024
#define NHEAD 16
#define HEADD 64
#define MROWS (BATCH * SEQ)   // 4096
#define GK    1024
#define GN    1024

#define LOG2E 1.4426950408889634f

// Scratch (device globals, fp16). g_v holds V TRANSPOSED: [b][h*64+d][2048]
__device__ __half g_q[MROWS * HDIM];
__device__ __half g_k[MROWS * HDIM];
__device__ __half g_v[MROWS * HDIM];
__device__ __half g_ctx[MROWS * HDIM];

__device__ __forceinline__ uint32_t packh2(float a, float b) {
    __half2 h = __floats2half2_rn(a, b);
    return *(uint32_t*)&h;
}
__device__ __forceinline__ float ex2(float x) {
    float r;
    asm("ex2.approx.f32 %0, %1;" : "=f"(r) : "f"(x));
    return r;
}
__device__ __forceinline__ void mma_f16(float d[4],
                                        uint32_t a0, uint32_t a1,
                                        uint32_t a2, uint32_t a3,
                                        uint32_t b0, uint32_t b1) {
    asm volatile(
        "mma.sync.aligned.m16n8k16.row.col.f32.f16.f16.f32 "
        "{%0,%1,%2,%3}, {%4,%5,%6,%7}, {%8,%9}, {%0,%1,%2,%3};"
        : "+f"(d[0]), "+f"(d[1]), "+f"(d[2]), "+f"(d[3])
        : "r"(a0), "r"(a1), "r"(a2), "r"(a3), "r"(b0), "r"(b1));
}

// ---------------------------------------------------------------------------
// fp16 GEMM core: acc = A[bm:+128] @ W[bn:+128]^T, K=1024, K-chunk 32.
// 256 thr / 8 warps (4M x 2N), warp tile 32x64, mma m16n8k16.
// Smem packs (halves): A slot (mt,ks,g,t) 16B = full A-frag {a0,a1,a2,a3};
// B slot (nidx,g,t) 16B = {b0,b1}ks0 + {b0,b1}ks1. Slots consecutive -> CF.
// ---------------------------------------------------------------------------
template <bool AHALF>
__device__ __forceinline__ void gemm_core_f16(const void* Avoid,
                                              const float* __restrict__ W,
                                              uint4* APack, uint4* BPack,
                                              float acc[2][8][4],
                                              int bm, int bn)
{
    const int tid  = threadIdx.x;
    const int wid  = tid >> 5;
    const int lane = tid & 31;
    const int g    = lane >> 2;
    const int t    = lane & 3;
    const int wm   = wid & 3;
    const int wn   = wid >> 2;

#pragma unroll
    for (int mi = 0; mi < 2; mi++)
#pragma unroll
        for (int nt = 0; nt < 8; nt++)
#pragma unroll
            for (int x = 0; x < 4; x++) acc[mi][nt][x] = 0.0f;

    // Decode this thread's 2 A-slots and 2 B-slots
    const void*  aP0[2];
    const void*  aP1[2];
    const float* bP[2];
    int slotIdx[2];
#pragma unroll
    for (int i = 0; i < 2; i++) {
        const int s  = tid + 256 * i;
        const int st = s & 3;
        const int sg = (s >> 2) & 7;
        const int q  = s >> 5;            // A: ks=q&1, mt=q>>1 ; B: nidx=q
        slotIdx[i] = s;
        const int r0  = bm + 16 * (q >> 1) + sg;
        const int col = 16 * (q & 1) + 2 * st;
        if (AHALF) {
            const __half* A = (const __half*)Avoid;
            aP0[i] = A + (size_t)r0 * GK + col;
            aP1[i] = A + (size_t)(r0 + 8) * GK + col;
        } else {
            const float* A = (const float*)Avoid;
            aP0[i] = A + (size_t)r0 * GK + col;
            aP1[i] = A + (size_t)(r0 + 8) * GK + col;
        }
        bP[i] = W + (size_t)(bn + 8 * q + sg) * GK + 2 * st;
    }

    float2   fa[2][4];
    uint32_t ha[2][4];
    float2   fb[2][4];

    // prefetch it=0
#pragma unroll
    for (int i = 0; i < 2; i++) {
        if (AHALF) {
            const __half* p0 = (const __half*)aP0[i];
            const __half* p1 = (const __half*)aP1[i];
            ha[i][0] = *(const uint32_t*)p0;
            ha[i][1] = *(const uint32_t*)p1;
            ha[i][2] = *(const uint32_t*)(p0 + 8);
            ha[i][3] = *(const uint32_t*)(p1 + 8);
        } else {
            const float* p0 = (const float*)aP0[i];
            const float* p1 = (const float*)aP1[i];
            fa[i][0] = *(const float2*)p0;
            fa[i][1] = *(const float2*)p1;
            fa[i][2] = *(const float2*)(p0 + 8);
            fa[i][3] = *(const float2*)(p1 + 8);
        }
        const float* pb = bP[i];
        fb[i][0] = *(const float2*)pb;
        fb[i][1] = *(const float2*)(pb + 8);
        fb[i][2] = *(const float2*)(pb + 16);
        fb[i][3] = *(const float2*)(pb + 24);
    }

    for (int it = 0; it < GK / 32; ++it) {
        // store staged slots
#pragma unroll
        for (int i = 0; i < 2; i++) {
            uint4 va;
            if (AHALF) {
                va = make_uint4(ha[i][0], ha[i][1], ha[i][2], ha[i][3]);
            } else {
                va = make_uint4(packh2(fa[i][0].x, fa[i][0].y),
                                packh2(fa[i][1].x, fa[i][1].y),
                                packh2(fa[i][2].x, fa[i][2].y),
                                packh2(fa[i][3].x, fa[i][3].y));
            }
            APack[slotIdx[i]] = va;
            BPack[slotIdx[i]] = make_uint4(packh2(fb[i][0].x, fb[i][0].y),
                                           packh2(fb[i][1].x, fb[i][1].y),
                                           packh2(fb[i][2].x, fb[i][2].y),
                                           packh2(fb[i][3].x, fb[i][3].y));
        }
        __syncthreads();

        if (it + 1 < GK / 32) {
            const int ko = (it + 1) * 32;
#pragma unroll
            for (int i = 0; i < 2; i++) {
                if (AHALF) {
                    const __half* p0 = (const __half*)aP0[i] + ko;
                    const __half* p1 = (const __half*)aP1[i] + ko;
                    ha[i][0] = *(const uint32_t*)p0;
                    ha[i][1] = *(const uint32_t*)p1;
                    ha[i][2] = *(const uint32_t*)(p0 + 8);
                    ha[i][3] = *(const uint32_t*)(p1 + 8);
                } else {
                    const float* p0 = (const float*)aP0[i] + ko;
                    const float* p1 = (const float*)aP1[i] + ko;
                    fa[i][0] = *(const float2*)p0;
                    fa[i][1] = *(const float2*)p1;
                    fa[i][2] = *(const float2*)(p0 + 8);
                    fa[i][3] = *(const float2*)(p1 + 8);
                }
                const float* pb = bP[i] + ko;
                fb[i][0] = *(const float2*)pb;
                fb[i][1] = *(const float2*)(pb + 8);
                fb[i][2] = *(const float2*)(pb + 16);
                fb[i][3] = *(const float2*)(pb + 24);
            }
        }

        // mma: A frags (mi,ks), B frags (nt) cover both ks
        uint4 aF[2][2];
#pragma unroll
        for (int mi = 0; mi < 2; mi++)
#pragma unroll
            for (int ks = 0; ks < 2; ks++)
                aF[mi][ks] = APack[(((wm * 2 + mi) * 2 + ks) * 8 + g) * 4 + t];
#pragma unroll
        for (int nt = 0; nt < 8; nt++) {
            uint4 bF = BPack[((wn * 8 + nt) * 8 + g) * 4 + t];
            mma_f16(acc[0][nt], aF[0][0].x, aF[0][0].y, aF[0][0].z, aF[0][0].w, bF.x, bF.y);
            mma_f16(acc[1][nt], aF[1][0].x, aF[1][0].y, aF[1][0].z, aF[1][0].w, bF.x, bF.y);
            mma_f16(acc[0][nt], aF[0][1].x, aF[0][1].y, aF[0][1].z, aF[0][1].w, bF.z, bF.w);
            mma_f16(acc[1][nt], aF[1][1].x, aF[1][1].y, aF[1][1].z, aF[1][1].w, bF.z, bF.w);
        }
        __syncthreads();
    }
}

// Fused QKV: grid.x in [0,24): sel = x>>3 (0=Q,1=K,2=V), bn = (x&7)*128.
__global__ __launch_bounds__(256, 2)
void qkv_kernel(const float* __restrict__ hs,
                const float* __restrict__ Wq, const float* __restrict__ bq,
                const float* __restrict__ Wk, const float* __restrict__ bk,
                const float* __restrict__ Wv, const float* __restrict__ bv,
                __half* __restrict__ Cq, __half* __restrict__ Ck,
                __half* __restrict__ CvT)
{
    __shared__ uint4 APack[512];
    __shared__ uint4 BPack[512];

    const int sel = blockIdx.x >> 3;
    const int bn  = (blockIdx.x & 7) * 128;
    const int bm  = blockIdx.y * 128;
    const float* W    = (sel == 0) ? Wq : (sel == 1) ? Wk : Wv;
    const float* bias = (sel == 0) ? bq : (sel == 1) ? bk : bv;

    float acc[2][8][4];
    gemm_core_f16<false>(hs, W, APack, BPack, acc, bm, bn);

    const int lane = threadIdx.x & 31;
    const int wid  = threadIdx.x >> 5;
    const int g    = lane >> 2;
    const int t    = lane & 3;
    const int wm   = wid & 3;
    const int wn   = wid >> 2;

    if (sel < 2) {
        __half* C = (sel == 0) ? Cq : Ck;
#pragma unroll
        for (int mi = 0; mi < 2; mi++) {
            const int row0 = bm + wm * 32 + mi * 16 + g;
#pragma unroll
            for (int nt = 0; nt < 8; nt++) {
                const int col = bn + wn * 64 + nt * 8 + 2 * t;
                const float2 bv2 = *(const float2*)(bias + col);
                *(uint32_t*)(C + (size_t)row0 * GN + col) =
                    packh2(acc[mi][nt][0] + bv2.x, acc[mi][nt][1] + bv2.y);
                *(uint32_t*)(C + (size_t)(row0 + 8) * GN + col) =
                    packh2(acc[mi][nt][2] + bv2.x, acc[mi][nt][3] + bv2.y);
            }
        }
    } else {
        // transposed V store: CvT[(bidx*1024 + col)*2048 + j]
#pragma unroll
        for (int mi = 0; mi < 2; mi++) {
            const int row0 = bm + wm * 32 + mi * 16 + g;
            const int bidx = row0 >> 11;
            const int j    = row0 & 2047;
#pragma unroll
            for (int nt = 0; nt < 8; nt++) {
                const int col = bn + wn * 64 + nt * 8 + 2 * t;
                const float2 bv2 = *(const float2*)(bias + col);
                __half* base0 = CvT + (size_t)(bidx * 1024 + col) * 2048;
                __half* base1 = CvT + (size_t)(bidx * 1024 + col + 1) * 2048;
                base0[j]     = __float2half_rn(acc[mi][nt][0] + bv2.x);
                base1[j]     = __float2half_rn(acc[mi][nt][1] + bv2.y);
                base0[j + 8] = __float2half_rn(acc[mi][nt][2] + bv2.x);
                base1[j + 8] = __float2half_rn(acc[mi][nt][3] + bv2.y);
            }
        }
    }
}

// Output projection: A = ctx (fp16), W fp32, C fp32 out.
__global__ __launch_bounds__(256, 2)
void gemm_out_kernel(const __half* __restrict__ A,
                     const float* __restrict__ W,
                     const float* __restrict__ bias,
                     float* __restrict__ C)
{
    __shared__ uint4 APack[512];
    __shared__ uint4 BPack[512];

    const int bn = blockIdx.x * 128;
    const int bm = blockIdx.y * 128;

    float acc[2][8][4];
    gemm_core_f16<true>(A, W, APack, BPack, acc, bm, bn);

    const int lane = threadIdx.x & 31;
    const int wid  = threadIdx.x >> 5;
    const int g    = lane >> 2;
    const int t    = lane & 3;
    const int wm   = wid & 3;
    const int wn   = wid >> 2;

#pragma unroll
    for (int mi = 0; mi < 2; mi++) {
        const int row0 = bm + wm * 32 + mi * 16 + g;
#pragma unroll
        for (int nt = 0; nt < 8; nt++) {
            const int col = bn + wn * 64 + nt * 8 + 2 * t;
            const float2 bv2 = *(const float2*)(bias + col);
            float2 o0, o1;
            o0.x = acc[mi][nt][0] + bv2.x; o0.y = acc[mi][nt][1] + bv2.y;
            o1.x = acc[mi][nt][2] + bv2.x; o1.y = acc[mi][nt][3] + bv2.y;
            *(float2*)(C + (size_t)row0 * GN + col)       = o0;
            *(float2*)(C + (size_t)(row0 + 8) * GN + col) = o1;
        }
    }
}

// ---------------------------------------------------------------------------
// fp16 flash attention: 256 thr / 8 warps, warp = 16 q-rows, chunk 64 keys.
// Q fragments loaded directly from gmem (half). K/V staged as raw uint4
// copies into fragment-slot layout (no conversion, no swizzle, CF).
// S-accum fragment layout == PV A-fragment layout (fp16 identity): no shfl.
// ---------------------------------------------------------------------------
__global__ __launch_bounds__(256, 2)
void attn_f16_kernel(const __half* __restrict__ Q,
                     const __half* __restrict__ Kg,
                     const __half* __restrict__ VT,
                     const float* __restrict__ mask,
                     __half* __restrict__ ctx)
{
    __shared__ uint4 KP[512];
    __shared__ uint4 VP[512];
    __shared__ float msk[64];

    const int tid  = threadIdx.x;
    const int lane = tid & 31;
    const int wid  = tid >> 5;
    const int g    = lane >> 2;
    const int t    = lane & 3;
    const int bh   = blockIdx.y;
    const int b    = bh >> 4;
    const int h    = bh & 15;
    const int q0   = blockIdx.x * 128;
    const int wq   = wid * 16;

    const float SC = 0.125f * LOG2E;

    // --- Persistent Q fragments (direct gmem loads) ---
    uint32_t qf[4][4];
    {
        const __half* Qb = Q + (size_t)(b * SEQ + q0 + wq + g) * HDIM + h * 64 + 2 * t;
#pragma unroll
        for (int ks = 0; ks < 4; ks++) {
            qf[ks][0] = *(const uint32_t*)(Qb + 16 * ks);
            qf[ks][1] = *(const uint32_t*)(Qb + 8 * HDIM + 16 * ks);
            qf[ks][2] = *(const uint32_t*)(Qb + 16 * ks + 8);
            qf[ks][3] = *(const uint32_t*)(Qb + 8 * HDIM + 16 * ks + 8);
        }
    }

    // --- Staging pointers (2 K slots + 2 V slots per thread) ---
    const __half* kPtr[2];
    const __half* vPtr[2];
#pragma unroll
    for (int i = 0; i < 2; i++) {
        const int s   = tid + 256 * i;
        const int st  = s & 3;
        const int sg  = (s >> 2) & 7;
        const int ksp = (s >> 5) & 1;
        const int blk = s >> 6;          // jt for K, dt for V
        kPtr[i] = Kg + (size_t)(b * SEQ + 8 * blk + sg) * HDIM
                     + h * 64 + 32 * ksp + 2 * st;
        vPtr[i] = VT + (size_t)(b * 1024 + h * 64 + 8 * blk + sg) * 2048
                     + 32 * ksp + 2 * st;
    }

    float oacc[8][4];
#pragma unroll
    for (int nt = 0; nt < 8; nt++)
#pragma unroll
        for (int x = 0; x < 4; x++) oacc[nt][x] = 0.0f;
    float lsum0 = 0.0f, lsum1 = 0.0f;

    for (int k0 = 0; k0 < SEQ; k0 += 64) {
        // --- Stage K and V slots (raw half copies) ---
#pragma unroll
        for (int i = 0; i < 2; i++) {
            const __half* p = kPtr[i];
            KP[tid + 256 * i] = make_uint4(*(const uint32_t*)(p),
                                           *(const uint32_t*)(p + 8),
                                           *(const uint32_t*)(p + 16),
                                           *(const uint32_t*)(p + 24));
            const __half* q = vPtr[i];
            VP[tid + 256 * i] = make_uint4(*(const uint32_t*)(q),
                                           *(const uint32_t*)(q + 8),
                                           *(const uint32_t*)(q + 16),
                                           *(const uint32_t*)(q + 24));
            kPtr[i] += 64 * HDIM;
            vPtr[i] += 64;
        }
        if (tid < 64) msk[tid] = mask[(size_t)b * SEQ + k0 + tid] * LOG2E;
        __syncthreads();

        // --- S = Q @ K^T ---
        float sacc[8][4];
#pragma unroll
        for (int nt = 0; nt < 8; nt++)
#pragma unroll
            for (int x = 0; x < 4; x++) sacc[nt][x] = 0.0f;

#pragma unroll
        for (int nt = 0; nt < 8; nt++) {
#pragma unroll
            for (int ksp = 0; ksp < 2; ksp++) {
                uint4 bF = KP[((nt * 2 + ksp) * 8 + g) * 4 + t];
                mma_f16(sacc[nt], qf[2*ksp][0], qf[2*ksp][1], qf[2*ksp][2], qf[2*ksp][3],
                        bF.x, bF.y);
                mma_f16(sacc[nt], qf[2*ksp+1][0], qf[2*ksp+1][1], qf[2*ksp+1][2], qf[2*ksp+1][3],
                        bF.z, bF.w);
            }
        }

        // --- softmax numerators (single-pass, exp2) ---
#pragma unroll
        for (int nt = 0; nt < 8; nt++) {
            float2 mk = *(const float2*)&msk[nt * 8 + 2 * t];
            float e0 = ex2(fmaf(sacc[nt][0], SC, mk.x));
            float e1 = ex2(fmaf(sacc[nt][1], SC, mk.y));
            float e2 = ex2(fmaf(sacc[nt][2], SC, mk.x));
            float e3 = ex2(fmaf(sacc[nt][3], SC, mk.y));
            lsum0 += e0 + e1;
            lsum1 += e2 + e3;
            sacc[nt][0] = e0; sacc[nt][1] = e1;
            sacc[nt][2] = e2; sacc[nt][3] = e3;
        }

        // --- P fragments: C-layout == A-layout for fp16 (no shfl) ---
        uint32_t pf[4][4];
#pragma unroll
        for (int ks = 0; ks < 4; ks++) {
            pf[ks][0] = packh2(sacc[2*ks][0],   sacc[2*ks][1]);
            pf[ks][1] = packh2(sacc[2*ks][2],   sacc[2*ks][3]);
            pf[ks][2] = packh2(sacc[2*ks+1][0], sacc[2*ks+1][1]);
            pf[ks][3] = packh2(sacc[2*ks+1][2], sacc[2*ks+1][3]);
        }

        // --- O += P @ V ---
#pragma unroll
        for (int dt = 0; dt < 8; dt++) {
#pragma unroll
            for (int ksp = 0; ksp < 2; ksp++) {
                uint4 bF = VP[((dt * 2 + ksp) * 8 + g) * 4 + t];
                mma_f16(oacc[dt], pf[2*ksp][0], pf[2*ksp][1], pf[2*ksp][2], pf[2*ksp][3],
                        bF.x, bF.y);
                mma_f16(oacc[dt], pf[2*ksp+1][0], pf[2*ksp+1][1], pf[2*ksp+1][2], pf[2*ksp+1][3],
                        bF.z, bF.w);
            }
        }
        __syncthreads();
    }

    // --- Reduce row sums over t lanes, normalize, store fp16 ctx ---
    lsum0 += __shfl_xor_sync(0xffffffffu, lsum0, 1);
    lsum0 += __shfl_xor_sync(0xffffffffu, lsum0, 2);
    lsum1 += __shfl_xor_sync(0xffffffffu, lsum1, 1);
    lsum1 += __shfl_xor_sync(0xffffffffu, lsum1, 2);
    const float inv0 = 1.0f / lsum0;
    const float inv1 = 1.0f / lsum1;

    __half* c0 = ctx + (size_t)(b * SEQ + q0 + wq + g) * HDIM + h * 64 + 2 * t;
#pragma unroll
    for (int dt = 0; dt < 8; dt++) {
        *(uint32_t*)(c0 + 8 * dt) =
            packh2(oacc[dt][0] * inv0, oacc[dt][1] * inv0);
        *(uint32_t*)(c0 + 8 * HDIM + 8 * dt) =
            packh2(oacc[dt][2] * inv1, oacc[dt][3] * inv1);
    }
}

// ---------------------------------------------------------------------------
// Launch
// ---------------------------------------------------------------------------
extern "C" void kernel_launch(void* const* d_in, const int* in_sizes, int n_in,
                              void* d_out, int out_size)
{
    const float* hs   = (const float*)d_in[0];
    const float* mask = (const float*)d_in[1];
    const float* Wq   = (const float*)d_in[2];
    const float* bq   = (const float*)d_in[3];
    const float* Wk   = (const float*)d_in[4];
    const float* bk   = (const float*)d_in[5];
    const float* Wv   = (const float*)d_in[6];
    const float* bv   = (const float*)d_in[7];
    const float* Wo   = (const float*)d_in[8];
    const float* bo   = (const float*)d_in[9];
    float* out = (float*)d_out;

    __half *qp, *kp, *vp, *cp;
    cudaGetSymbolAddress((void**)&qp, g_q);
    cudaGetSymbolAddress((void**)&kp, g_k);
    cudaGetSymbolAddress((void**)&vp, g_v);
    cudaGetSymbolAddress((void**)&cp, g_ctx);

    qkv_kernel<<<dim3(24, 32), dim3(256)>>>(hs, Wq, bq, Wk, bk, Wv, bv,
                                            qp, kp, vp);

    attn_f16_kernel<<<dim3(SEQ / 128, BATCH * NHEAD), dim3(256)>>>(
        qp, kp, vp, mask, cp);

    gemm_out_kernel<<<dim3(8, 32), dim3(256)>>>(cp, Wo, bo, out);
}

// round 14
// speedup vs baseline: 1.8563x; 1.0094x over previous
#include <cuda_runtime.h>
#include <cuda_fp16.h>
#include <math.h>
#include <stdint.h>

// Problem constants
#define BATCH 2
#define SEQ   2048
#define HDIM  1024
#define NHEAD 16
#define HEADD 64
#define MROWS (BATCH * SEQ)   // 4096
#define GK    1024
#define GN    1024

#define LOG2E 1.4426950408889634f

// Scratch (device globals, fp16). g_v holds V TRANSPOSED: [b][h*64+d][2048]
__device__ __half g_q[MROWS * HDIM];
__device__ __half g_k[MROWS * HDIM];
__device__ __half g_v[MROWS * HDIM];
__device__ __half g_ctx[MROWS * HDIM];
__device__ __half g_hs[MROWS * HDIM];        // hiddenStates in fp16
__device__ __half g_w[4][GK * GN];           // Wq, Wk, Wv, Wo in fp16

__device__ __forceinline__ uint32_t packh2(float a, float b) {
    __half2 h = __floats2half2_rn(a, b);
    return *(uint32_t*)&h;
}
__device__ __forceinline__ float ex2(float x) {
    float r;
    asm("ex2.approx.f32 %0, %1;" : "=f"(r) : "f"(x));
    return r;
}
__device__ __forceinline__ void mma_f16(float d[4],
                                        uint32_t a0, uint32_t a1,
                                        uint32_t a2, uint32_t a3,
                                        uint32_t b0, uint32_t b1) {
    asm volatile(
        "mma.sync.aligned.m16n8k16.row.col.f32.f16.f16.f32 "
        "{%0,%1,%2,%3}, {%4,%5,%6,%7}, {%8,%9}, {%0,%1,%2,%3};"
        : "+f"(d[0]), "+f"(d[1]), "+f"(d[2]), "+f"(d[3])
        : "r"(a0), "r"(a1), "r"(a2), "r"(a3), "r"(b0), "r"(b1));
}

// ---------------------------------------------------------------------------
// fp32 -> fp16 conversion (grid-stride, vectorized)
// ---------------------------------------------------------------------------
__global__ void cvt_f2h(const float* __restrict__ src,
                        __half* __restrict__ dst, int n4)
{
    int i = blockIdx.x * blockDim.x + threadIdx.x;
    const int stride = gridDim.x * blockDim.x;
    for (; i < n4; i += stride) {
        float4 v = ((const float4*)src)[i];
        uint2 o;
        o.x = packh2(v.x, v.y);
        o.y = packh2(v.z, v.w);
        ((uint2*)dst)[i] = o;
    }
}

// ---------------------------------------------------------------------------
// fp16 GEMM core: acc = A[bm:+128] @ W[bn:+128]^T, K=1024, K-chunk 32.
// Both operands fp16 in gmem. 256 thr / 8 warps (4M x 2N), warp tile 32x64.
// Smem slot layout (16B per slot, consecutive -> conflict-free):
//   A slot (mt,ks,g,t): full A-frag {a0,a1,a2,a3}
//   B slot (nidx,g,t):  {b0,b1}ks0 + {b0,b1}ks1
// Staging = raw uint32 copies (no conversion in loop), register double-buffer.
// ---------------------------------------------------------------------------
__device__ __forceinline__ void gemm_core_h(const __half* __restrict__ A,
                                            const __half* __restrict__ W,
                                            uint4* APack, uint4* BPack,
                                            float acc[2][8][4],
                                            int bm, int bn)
{
    const int tid  = threadIdx.x;
    const int wid  = tid >> 5;
    const int lane = tid & 31;
    const int g    = lane >> 2;
    const int t    = lane & 3;
    const int wm   = wid & 3;
    const int wn   = wid >> 2;

#pragma unroll
    for (int mi = 0; mi < 2; mi++)
#pragma unroll
        for (int nt = 0; nt < 8; nt++)
#pragma unroll
            for (int x = 0; x < 4; x++) acc[mi][nt][x] = 0.0f;

    // Decode this thread's 2 A-slots and 2 B-slots
    const __half* aP0[2];
    const __half* aP1[2];
    const __half* bP[2];
#pragma unroll
    for (int i = 0; i < 2; i++) {
        const int s  = tid + 256 * i;
        const int st = s & 3;
        const int sg = (s >> 2) & 7;
        const int q  = s >> 5;            // A: ks=q&1, mt=q>>1 ; B: nidx=q
        const int r0  = bm + 16 * (q >> 1) + sg;
        const int col = 16 * (q & 1) + 2 * st;
        aP0[i] = A + (size_t)r0 * GK + col;
        aP1[i] = A + (size_t)(r0 + 8) * GK + col;
        bP[i]  = W + (size_t)(bn + 8 * q + sg) * GK + 2 * st;
    }

    uint32_t ha[2][4], hb[2][4];

    // prefetch it=0
#pragma unroll
    for (int i = 0; i < 2; i++) {
        ha[i][0] = *(const uint32_t*)(aP0[i]);
        ha[i][1] = *(const uint32_t*)(aP1[i]);
        ha[i][2] = *(const uint32_t*)(aP0[i] + 8);
        ha[i][3] = *(const uint32_t*)(aP1[i] + 8);
        hb[i][0] = *(const uint32_t*)(bP[i]);
        hb[i][1] = *(const uint32_t*)(bP[i] + 8);
        hb[i][2] = *(const uint32_t*)(bP[i] + 16);
        hb[i][3] = *(const uint32_t*)(bP[i] + 24);
    }

    for (int it = 0; it < GK / 32; ++it) {
#pragma unroll
        for (int i = 0; i < 2; i++) {
            const int s = tid + 256 * i;
            APack[s] = make_uint4(ha[i][0], ha[i][1], ha[i][2], ha[i][3]);
            BPack[s] = make_uint4(hb[i][0], hb[i][1], hb[i][2], hb[i][3]);
        }
        __syncthreads();

        if (it + 1 < GK / 32) {
            const int ko = (it + 1) * 32;
#pragma unroll
            for (int i = 0; i < 2; i++) {
                ha[i][0] = *(const uint32_t*)(aP0[i] + ko);
                ha[i][1] = *(const uint32_t*)(aP1[i] + ko);
                ha[i][2] = *(const uint32_t*)(aP0[i] + ko + 8);
                ha[i][3] = *(const uint32_t*)(aP1[i] + ko + 8);
                hb[i][0] = *(const uint32_t*)(bP[i] + ko);
                hb[i][1] = *(const uint32_t*)(bP[i] + ko + 8);
                hb[i][2] = *(const uint32_t*)(bP[i] + ko + 16);
                hb[i][3] = *(const uint32_t*)(bP[i] + ko + 24);
            }
        }

        uint4 aF[2][2];
#pragma unroll
        for (int mi = 0; mi < 2; mi++)
#pragma unroll
            for (int ks = 0; ks < 2; ks++)
                aF[mi][ks] = APack[(((wm * 2 + mi) * 2 + ks) * 8 + g) * 4 + t];
#pragma unroll
        for (int nt = 0; nt < 8; nt++) {
            uint4 bF = BPack[((wn * 8 + nt) * 8 + g) * 4 + t];
            mma_f16(acc[0][nt], aF[0][0].x, aF[0][0].y, aF[0][0].z, aF[0][0].w, bF.x, bF.y);
            mma_f16(acc[1][nt], aF[1][0].x, aF[1][0].y, aF[1][0].z, aF[1][0].w, bF.x, bF.y);
            mma_f16(acc[0][nt], aF[0][1].x, aF[0][1].y, aF[0][1].z, aF[0][1].w, bF.z, bF.w);
            mma_f16(acc[1][nt], aF[1][1].x, aF[1][1].y, aF[1][1].z, aF[1][1].w, bF.z, bF.w);
        }
        __syncthreads();
    }
}

// Fused QKV: grid.x in [0,24): sel = x>>3 (0=Q,1=K,2=V), bn = (x&7)*128.
__global__ __launch_bounds__(256, 2)
void qkv_kernel(const __half* __restrict__ hs16,
                const __half* __restrict__ w16,   // base of g_w
                const float* __restrict__ bq,
                const float* __restrict__ bk,
                const float* __restrict__ bv,
                __half* __restrict__ Cq, __half* __restrict__ Ck,
                __half* __restrict__ CvT)
{
    __shared__ uint4 APack[512];
    __shared__ uint4 BPack[512];

    const int sel = blockIdx.x >> 3;
    const int bn  = (blockIdx.x & 7) * 128;
    const int bm  = blockIdx.y * 128;
    const __half* W    = w16 + (size_t)sel * GK * GN;
    const float*  bias = (sel == 0) ? bq : (sel == 1) ? bk : bv;

    float acc[2][8][4];
    gemm_core_h(hs16, W, APack, BPack, acc, bm, bn);

    const int lane = threadIdx.x & 31;
    const int wid  = threadIdx.x >> 5;
    const int g    = lane >> 2;
    const int t    = lane & 3;
    const int wm   = wid & 3;
    const int wn   = wid >> 2;

    if (sel < 2) {
        __half* C = (sel == 0) ? Cq : Ck;
#pragma unroll
        for (int mi = 0; mi < 2; mi++) {
            const int row0 = bm + wm * 32 + mi * 16 + g;
#pragma unroll
            for (int nt = 0; nt < 8; nt++) {
                const int col = bn + wn * 64 + nt * 8 + 2 * t;
                const float2 bv2 = *(const float2*)(bias + col);
                *(uint32_t*)(C + (size_t)row0 * GN + col) =
                    packh2(acc[mi][nt][0] + bv2.x, acc[mi][nt][1] + bv2.y);
                *(uint32_t*)(C + (size_t)(row0 + 8) * GN + col) =
                    packh2(acc[mi][nt][2] + bv2.x, acc[mi][nt][3] + bv2.y);
            }
        }
    } else {
        // transposed V store: CvT[(bidx*1024 + col)*2048 + j]
#pragma unroll
        for (int mi = 0; mi < 2; mi++) {
            const int row0 = bm + wm * 32 + mi * 16 + g;
            const int bidx = row0 >> 11;
            const int j    = row0 & 2047;
#pragma unroll
            for (int nt = 0; nt < 8; nt++) {
                const int col = bn + wn * 64 + nt * 8 + 2 * t;
                const float2 bv2 = *(const float2*)(bias + col);
                __half* base0 = CvT + (size_t)(bidx * 1024 + col) * 2048;
                __half* base1 = CvT + (size_t)(bidx * 1024 + col + 1) * 2048;
                base0[j]     = __float2half_rn(acc[mi][nt][0] + bv2.x);
                base1[j]     = __float2half_rn(acc[mi][nt][1] + bv2.y);
                base0[j + 8] = __float2half_rn(acc[mi][nt][2] + bv2.x);
                base1[j + 8] = __float2half_rn(acc[mi][nt][3] + bv2.y);
            }
        }
    }
}

// Output projection: ctx (fp16) @ Wo16^T + bo -> fp32 out.
__global__ __launch_bounds__(256, 2)
void gemm_out_kernel(const __half* __restrict__ A,
                     const __half* __restrict__ W,
                     const float* __restrict__ bias,
                     float* __restrict__ C)
{
    __shared__ uint4 APack[512];
    __shared__ uint4 BPack[512];

    const int bn = blockIdx.x * 128;
    const int bm = blockIdx.y * 128;

    float acc[2][8][4];
    gemm_core_h(A, W, APack, BPack, acc, bm, bn);

    const int lane = threadIdx.x & 31;
    const int wid  = threadIdx.x >> 5;
    const int g    = lane >> 2;
    const int t    = lane & 3;
    const int wm   = wid & 3;
    const int wn   = wid >> 2;

#pragma unroll
    for (int mi = 0; mi < 2; mi++) {
        const int row0 = bm + wm * 32 + mi * 16 + g;
#pragma unroll
        for (int nt = 0; nt < 8; nt++) {
            const int col = bn + wn * 64 + nt * 8 + 2 * t;
            const float2 bv2 = *(const float2*)(bias + col);
            float2 o0, o1;
            o0.x = acc[mi][nt][0] + bv2.x; o0.y = acc[mi][nt][1] + bv2.y;
            o1.x = acc[mi][nt][2] + bv2.x; o1.y = acc[mi][nt][3] + bv2.y;
            *(float2*)(C + (size_t)row0 * GN + col)       = o0;
            *(float2*)(C + (size_t)(row0 + 8) * GN + col) = o1;
        }
    }
}

// ---------------------------------------------------------------------------
// fp16 flash attention (unchanged from R12): 256 thr / 8 warps, warp = 16
// q-rows, chunk 64 keys. Raw fp16 staging; S-frag == PV A-frag (no shfl).
// ---------------------------------------------------------------------------
__global__ __launch_bounds__(256, 2)
void attn_f16_kernel(const __half* __restrict__ Q,
                     const __half* __restrict__ Kg,
                     const __half* __restrict__ VT,
                     const float* __restrict__ mask,
                     __half* __restrict__ ctx)
{
    __shared__ uint4 KP[512];
    __shared__ uint4 VP[512];
    __shared__ float msk[64];

    const int tid  = threadIdx.x;
    const int lane = tid & 31;
    const int wid  = tid >> 5;
    const int g    = lane >> 2;
    const int t    = lane & 3;
    const int bh   = blockIdx.y;
    const int b    = bh >> 4;
    const int h    = bh & 15;
    const int q0   = blockIdx.x * 128;
    const int wq   = wid * 16;

    const float SC = 0.125f * LOG2E;

    // --- Persistent Q fragments (direct gmem loads) ---
    uint32_t qf[4][4];
    {
        const __half* Qb = Q + (size_t)(b * SEQ + q0 + wq + g) * HDIM + h * 64 + 2 * t;
#pragma unroll
        for (int ks = 0; ks < 4; ks++) {
            qf[ks][0] = *(const uint32_t*)(Qb + 16 * ks);
            qf[ks][1] = *(const uint32_t*)(Qb + 8 * HDIM + 16 * ks);
            qf[ks][2] = *(const uint32_t*)(Qb + 16 * ks + 8);
            qf[ks][3] = *(const uint32_t*)(Qb + 8 * HDIM + 16 * ks + 8);
        }
    }

    // --- Staging pointers (2 K slots + 2 V slots per thread) ---
    const __half* kPtr[2];
    const __half* vPtr[2];
#pragma unroll
    for (int i = 0; i < 2; i++) {
        const int s   = tid + 256 * i;
        const int st  = s & 3;
        const int sg  = (s >> 2) & 7;
        const int ksp = (s >> 5) & 1;
        const int blk = s >> 6;          // jt for K, dt for V
        kPtr[i] = Kg + (size_t)(b * SEQ + 8 * blk + sg) * HDIM
                     + h * 64 + 32 * ksp + 2 * st;
        vPtr[i] = VT + (size_t)(b * 1024 + h * 64 + 8 * blk + sg) * 2048
                     + 32 * ksp + 2 * st;
    }

    float oacc[8][4];
#pragma unroll
    for (int nt = 0; nt < 8; nt++)
#pragma unroll
        for (int x = 0; x < 4; x++) oacc[nt][x] = 0.0f;
    float lsum0 = 0.0f, lsum1 = 0.0f;

    for (int k0 = 0; k0 < SEQ; k0 += 64) {
#pragma unroll
        for (int i = 0; i < 2; i++) {
            const __half* p = kPtr[i];
            KP[tid + 256 * i] = make_uint4(*(const uint32_t*)(p),
                                           *(const uint32_t*)(p + 8),
                                           *(const uint32_t*)(p + 16),
                                           *(const uint32_t*)(p + 24));
            const __half* q = vPtr[i];
            VP[tid + 256 * i] = make_uint4(*(const uint32_t*)(q),
                                           *(const uint32_t*)(q + 8),
                                           *(const uint32_t*)(q + 16),
                                           *(const uint32_t*)(q + 24));
            kPtr[i] += 64 * HDIM;
            vPtr[i] += 64;
        }
        if (tid < 64) msk[tid] = mask[(size_t)b * SEQ + k0 + tid] * LOG2E;
        __syncthreads();

        float sacc[8][4];
#pragma unroll
        for (int nt = 0; nt < 8; nt++)
#pragma unroll
            for (int x = 0; x < 4; x++) sacc[nt][x] = 0.0f;

#pragma unroll
        for (int nt = 0; nt < 8; nt++) {
#pragma unroll
            for (int ksp = 0; ksp < 2; ksp++) {
                uint4 bF = KP[((nt * 2 + ksp) * 8 + g) * 4 + t];
                mma_f16(sacc[nt], qf[2*ksp][0], qf[2*ksp][1], qf[2*ksp][2], qf[2*ksp][3],
                        bF.x, bF.y);
                mma_f16(sacc[nt], qf[2*ksp+1][0], qf[2*ksp+1][1], qf[2*ksp+1][2], qf[2*ksp+1][3],
                        bF.z, bF.w);
            }
        }

#pragma unroll
        for (int nt = 0; nt < 8; nt++) {
            float2 mk = *(const float2*)&msk[nt * 8 + 2 * t];
            float e0 = ex2(fmaf(sacc[nt][0], SC, mk.x));
            float e1 = ex2(fmaf(sacc[nt][1], SC, mk.y));
            float e2 = ex2(fmaf(sacc[nt][2], SC, mk.x));
            float e3 = ex2(fmaf(sacc[nt][3], SC, mk.y));
            lsum0 += e0 + e1;
            lsum1 += e2 + e3;
            sacc[nt][0] = e0; sacc[nt][1] = e1;
            sacc[nt][2] = e2; sacc[nt][3] = e3;
        }

        uint32_t pf[4][4];
#pragma unroll
        for (int ks = 0; ks < 4; ks++) {
            pf[ks][0] = packh2(sacc[2*ks][0],   sacc[2*ks][1]);
            pf[ks][1] = packh2(sacc[2*ks][2],   sacc[2*ks][3]);
            pf[ks][2] = packh2(sacc[2*ks+1][0], sacc[2*ks+1][1]);
            pf[ks][3] = packh2(sacc[2*ks+1][2], sacc[2*ks+1][3]);
        }

#pragma unroll
        for (int dt = 0; dt < 8; dt++) {
#pragma unroll
            for (int ksp = 0; ksp < 2; ksp++) {
                uint4 bF = VP[((dt * 2 + ksp) * 8 + g) * 4 + t];
                mma_f16(oacc[dt], pf[2*ksp][0], pf[2*ksp][1], pf[2*ksp][2], pf[2*ksp][3],
                        bF.x, bF.y);
                mma_f16(oacc[dt], pf[2*ksp+1][0], pf[2*ksp+1][1], pf[2*ksp+1][2], pf[2*ksp+1][3],
                        bF.z, bF.w);
            }
        }
        __syncthreads();
    }

    lsum0 += __shfl_xor_sync(0xffffffffu, lsum0, 1);
    lsum0 += __shfl_xor_sync(0xffffffffu, lsum0, 2);
    lsum1 += __shfl_xor_sync(0xffffffffu, lsum1, 1);
    lsum1 += __shfl_xor_sync(0xffffffffu, lsum1, 2);
    const float inv0 = 1.0f / lsum0;
    const float inv1 = 1.0f / lsum1;

    __half* c0 = ctx + (size_t)(b * SEQ + q0 + wq + g) * HDIM + h * 64 + 2 * t;
#pragma unroll
    for (int dt = 0; dt < 8; dt++) {
        *(uint32_t*)(c0 + 8 * dt) =
            packh2(oacc[dt][0] * inv0, oacc[dt][1] * inv0);
        *(uint32_t*)(c0 + 8 * HDIM + 8 * dt) =
            packh2(oacc[dt][2] * inv1, oacc[dt][3] * inv1);
    }
}

// ---------------------------------------------------------------------------
// Launch
// ---------------------------------------------------------------------------
extern "C" void kernel_launch(void* const* d_in, const int* in_sizes, int n_in,
                              void* d_out, int out_size)
{
    const float* hs   = (const float*)d_in[0];
    const float* mask = (const float*)d_in[1];
    const float* Wq   = (const float*)d_in[2];
    const float* bq   = (const float*)d_in[3];
    const float* Wk   = (const float*)d_in[4];
    const float* bk   = (const float*)d_in[5];
    const float* Wv   = (const float*)d_in[6];
    const float* bv   = (const float*)d_in[7];
    const float* Wo   = (const float*)d_in[8];
    const float* bo   = (const float*)d_in[9];
    float* out = (float*)d_out;

    __half *qp, *kp, *vp, *cp, *hsp, *wp;
    cudaGetSymbolAddress((void**)&qp, g_q);
    cudaGetSymbolAddress((void**)&kp, g_k);
    cudaGetSymbolAddress((void**)&vp, g_v);
    cudaGetSymbolAddress((void**)&cp, g_ctx);
    cudaGetSymbolAddress((void**)&hsp, g_hs);
    cudaGetSymbolAddress((void**)&wp, g_w);

    // fp32 -> fp16 pre-conversion (hs + 4 weight matrices)
    cvt_f2h<<<256, 256>>>(hs, hsp, MROWS * HDIM / 4);
    cvt_f2h<<<128, 256>>>(Wq, wp + 0 * (size_t)GK * GN, GK * GN / 4);
    cvt_f2h<<<128, 256>>>(Wk, wp + 1 * (size_t)GK * GN, GK * GN / 4);
    cvt_f2h<<<128, 256>>>(Wv, wp + 2 * (size_t)GK * GN, GK * GN / 4);
    cvt_f2h<<<128, 256>>>(Wo, wp + 3 * (size_t)GK * GN, GK * GN / 4);

    qkv_kernel<<<dim3(24, 32), dim3(256)>>>(hsp, wp, bq, bk, bv, qp, kp, vp);

    attn_f16_kernel<<<dim3(SEQ / 128, BATCH * NHEAD), dim3(256)>>>(
        qp, kp, vp, mask, cp);

    gemm_out_kernel<<<dim3(8, 32), dim3(256)>>>(
        cp, wp + 3 * (size_t)GK * GN, bo, out);
}

// round 16
// speedup vs baseline: 2.5447x; 1.3708x over previous
#include <cuda_runtime.h>
#include <cuda_fp16.h>
#include <math.h>
#include <stdint.h>

// Problem constants
#define BATCH 2
#define SEQ   2048
#define HDIM  1024
#define NHEAD 16
#define HEADD 64
#define MROWS (BATCH * SEQ)   // 4096
#define GK    1024
#define GN    1024

#define LOG2E 1.4426950408889634f

// Scratch (device globals, fp16). g_v holds V TRANSPOSED: [b][h*64+d][2048]
__device__ __half g_q[MROWS * HDIM];
__device__ __half g_k[MROWS * HDIM];
__device__ __half g_v[MROWS * HDIM];
__device__ __half g_ctx[MROWS * HDIM];
__device__ __half g_hs[MROWS * HDIM];
__device__ __half g_w[4][GK * GN];

__device__ __forceinline__ uint32_t packh2(float a, float b) {
    __half2 h = __floats2half2_rn(a, b);
    return *(uint32_t*)&h;
}
__device__ __forceinline__ float ex2(float x) {
    float r;
    asm("ex2.approx.f32 %0, %1;" : "=f"(r) : "f"(x));
    return r;
}
__device__ __forceinline__ uint32_t smem_u32(const void* p) {
    uint32_t a;
    asm("{ .reg .u64 t; cvta.to.shared.u64 t, %1; cvt.u32.u64 %0, t; }"
        : "=r"(a) : "l"(p));
    return a;
}
__device__ __forceinline__ void cp16(uint32_t dst, const void* src) {
    asm volatile("cp.async.cg.shared.global [%0], [%1], 16;"
                 :: "r"(dst), "l"(src));
}
__device__ __forceinline__ void cp_commit() {
    asm volatile("cp.async.commit_group;" ::: "memory");
}
__device__ __forceinline__ void cp_wait1() {
    asm volatile("cp.async.wait_group 1;" ::: "memory");
}
__device__ __forceinline__ void ldsm4(uint32_t r[4], uint32_t addr) {
    asm volatile("ldmatrix.sync.aligned.m8n8.x4.shared.b16 {%0,%1,%2,%3}, [%4];"
                 : "=r"(r[0]), "=r"(r[1]), "=r"(r[2]), "=r"(r[3]) : "r"(addr));
}
__device__ __forceinline__ void mma_f16(float d[4],
                                        uint32_t a0, uint32_t a1,
                                        uint32_t a2, uint32_t a3,
                                        uint32_t b0, uint32_t b1) {
    asm volatile(
        "mma.sync.aligned.m16n8k16.row.col.f32.f16.f16.f32 "
        "{%0,%1,%2,%3}, {%4,%5,%6,%7}, {%8,%9}, {%0,%1,%2,%3};"
        : "+f"(d[0]), "+f"(d[1]), "+f"(d[2]), "+f"(d[3])
        : "r"(a0), "r"(a1), "r"(a2), "r"(a3), "r"(b0), "r"(b1));
}

// ---------------------------------------------------------------------------
// Fused fp32 -> fp16 conversion: hs + 4 weight matrices in one launch.
// ---------------------------------------------------------------------------
__global__ void cvt_all(const float* __restrict__ hs,
                        const float* __restrict__ wq,
                        const float* __restrict__ wk,
                        const float* __restrict__ wv,
                        const float* __restrict__ wo,
                        __half* __restrict__ dhs,
                        __half* __restrict__ dw)
{
    const int HS4 = MROWS * HDIM / 4;   // 1048576
    const int W4  = GK * GN / 4;        // 262144
    const int TOT = HS4 + 4 * W4;
    int i = blockIdx.x * blockDim.x + threadIdx.x;
    const int stride = gridDim.x * blockDim.x;
    for (; i < TOT; i += stride) {
        const float* src;
        __half* dst;
        int off;
        if (i < HS4) {
            src = hs; dst = dhs; off = i;
        } else {
            int j = i - HS4;
            int sel = j >> 18;         // j / 262144
            off = j & (W4 - 1);
            src = (sel == 0) ? wq : (sel == 1) ? wk : (sel == 2) ? wv : wo;
            dst = dw + (size_t)sel * GK * GN;
        }
        float4 v = ((const float4*)src)[off];
        uint2 o;
        o.x = packh2(v.x, v.y);
        o.y = packh2(v.z, v.w);
        ((uint2*)dst)[off] = o;
    }
}

// ---------------------------------------------------------------------------
// Async fp16 GEMM core: acc = A[bm:+128] @ W[bn:+128]^T, K=1024.
// 3-stage cp.async pipeline, K-chunk 32; row-major smem tiles [128][32]h,
// 16B-unit XOR swizzle u ^= (row>>1)&3 (CF for stores and ldmatrix reads).
// Fragments via ldmatrix.x4. 256 thr / 8 warps (4M x 2N), warp tile 32x64.
// ---------------------------------------------------------------------------
#define NCHUNK (GK / 32)   // 32

__device__ __forceinline__ void gemm_core_async(const __half* __restrict__ A,
                                                const __half* __restrict__ W,
                                                uint4 (*sA)[512],
                                                uint4 (*sB)[512],
                                                float acc[2][8][4],
                                                int bm, int bn)
{
    const int tid  = threadIdx.x;
    const int wid  = tid >> 5;
    const int lane = tid & 31;
    const int wm   = wid & 3;
    const int wn   = wid >> 2;

#pragma unroll
    for (int mi = 0; mi < 2; mi++)
#pragma unroll
        for (int nt = 0; nt < 8; nt++)
#pragma unroll
            for (int x = 0; x < 4; x++) acc[mi][nt][x] = 0.0f;

    const uint32_t baseA = smem_u32(sA);
    const uint32_t baseB = smem_u32(sB);

    // staging: thread owns units v = tid, tid+256 (r = v>>2, c = v&3)
    const __half* gA[2];
    const __half* gB[2];
    uint32_t oA[2], oB[2];
#pragma unroll
    for (int i = 0; i < 2; i++) {
        const int v = tid + 256 * i;
        const int r = v >> 2;
        const int c = v & 3;
        gA[i] = A + (size_t)(bm + r) * GK + c * 8;
        gB[i] = W + (size_t)(bn + r) * GK + c * 8;
        const uint32_t sw = (uint32_t)(r * 4 + (c ^ ((r >> 1) & 3))) * 16;
        oA[i] = sw;
        oB[i] = sw;
    }

    // ldmatrix address components
    const int rowA = wm * 32 + ((lane >> 3) & 1) * 8 + (lane & 7);
    const int uaA  = (lane >> 4) & 1;
    const int xA   = (rowA >> 1) & 3;
    const int rowB = wn * 64 + ((lane >> 4) & 1) * 8 + (lane & 7);
    const int uaB  = (lane >> 3) & 1;
    const int xB   = (rowB >> 1) & 3;

    // prologue: issue chunks 0 and 1
#pragma unroll
    for (int s = 0; s < 2; s++) {
        const int k0 = s * 32;
#pragma unroll
        for (int i = 0; i < 2; i++) {
            cp16(baseA + s * 8192 + oA[i], gA[i] + k0);
            cp16(baseB + s * 8192 + oB[i], gB[i] + k0);
        }
        cp_commit();
    }

    for (int it = 0; it < NCHUNK; ++it) {
        cp_wait1();          // chunk it complete
        __syncthreads();     // visible to all; everyone done with slot (it-1)%3

        // issue chunk it+2 into slot (it+2)%3 (== (it-1)%3, freed by the sync)
        if (it + 2 < NCHUNK) {
            const int s  = (it + 2) % 3;
            const int k0 = (it + 2) * 32;
#pragma unroll
            for (int i = 0; i < 2; i++) {
                cp16(baseA + s * 8192 + oA[i], gA[i] + k0);
                cp16(baseB + s * 8192 + oB[i], gB[i] + k0);
            }
        }
        cp_commit();

        // compute on slot it%3
        const uint32_t stA = baseA + (it % 3) * 8192;
        const uint32_t stB = baseB + (it % 3) * 8192;
#pragma unroll
        for (int ks = 0; ks < 2; ks++) {
            uint32_t af[2][4];
#pragma unroll
            for (int mt = 0; mt < 2; mt++)
                ldsm4(af[mt], stA + (uint32_t)((rowA + mt * 16) * 4
                                 + ((2 * ks + uaA) ^ xA)) * 16);
#pragma unroll
            for (int p = 0; p < 4; p++) {
                uint32_t bf[4];
                ldsm4(bf, stB + (uint32_t)((rowB + p * 16) * 4
                              + ((2 * ks + uaB) ^ xB)) * 16);
                mma_f16(acc[0][2 * p],     af[0][0], af[0][1], af[0][2], af[0][3], bf[0], bf[1]);
                mma_f16(acc[1][2 * p],     af[1][0], af[1][1], af[1][2], af[1][3], bf[0], bf[1]);
                mma_f16(acc[0][2 * p + 1], af[0][0], af[0][1], af[0][2], af[0][3], bf[2], bf[3]);
                mma_f16(acc[1][2 * p + 1], af[1][0], af[1][1], af[1][2], af[1][3], bf[2], bf[3]);
            }
        }
    }
}

// Fused QKV: grid.x in [0,24): sel = x>>3 (0=Q,1=K,2=V), bn = (x&7)*128.
__global__ __launch_bounds__(256, 2)
void qkv_kernel(const __half* __restrict__ hs16,
                const __half* __restrict__ w16,
                const float* __restrict__ bq,
                const float* __restrict__ bk,
                const float* __restrict__ bv,
                __half* __restrict__ Cq, __half* __restrict__ Ck,
                __half* __restrict__ CvT)
{
    __shared__ uint4 sA[3][512];
    __shared__ uint4 sB[3][512];

    const int sel = blockIdx.x >> 3;
    const int bn  = (blockIdx.x & 7) * 128;
    const int bm  = blockIdx.y * 128;
    const __half* W    = w16 + (size_t)sel * GK * GN;
    const float*  bias = (sel == 0) ? bq : (sel == 1) ? bk : bv;

    float acc[2][8][4];
    gemm_core_async(hs16, W, sA, sB, acc, bm, bn);

    const int lane = threadIdx.x & 31;
    const int wid  = threadIdx.x >> 5;
    const int g    = lane >> 2;
    const int t    = lane & 3;
    const int wm   = wid & 3;
    const int wn   = wid >> 2;

    if (sel < 2) {
        __half* C = (sel == 0) ? Cq : Ck;
#pragma unroll
        for (int mi = 0; mi < 2; mi++) {
            const int row0 = bm + wm * 32 + mi * 16 + g;
#pragma unroll
            for (int nt = 0; nt < 8; nt++) {
                const int col = bn + wn * 64 + nt * 8 + 2 * t;
                const float2 bv2 = *(const float2*)(bias + col);
                *(uint32_t*)(C + (size_t)row0 * GN + col) =
                    packh2(acc[mi][nt][0] + bv2.x, acc[mi][nt][1] + bv2.y);
                *(uint32_t*)(C + (size_t)(row0 + 8) * GN + col) =
                    packh2(acc[mi][nt][2] + bv2.x, acc[mi][nt][3] + bv2.y);
            }
        }
    } else {
#pragma unroll
        for (int mi = 0; mi < 2; mi++) {
            const int row0 = bm + wm * 32 + mi * 16 + g;
            const int bidx = row0 >> 11;
            const int j    = row0 & 2047;
#pragma unroll
            for (int nt = 0; nt < 8; nt++) {
                const int col = bn + wn * 64 + nt * 8 + 2 * t;
                const float2 bv2 = *(const float2*)(bias + col);
                __half* base0 = CvT + (size_t)(bidx * 1024 + col) * 2048;
                __half* base1 = CvT + (size_t)(bidx * 1024 + col + 1) * 2048;
                base0[j]     = __float2half_rn(acc[mi][nt][0] + bv2.x);
                base1[j]     = __float2half_rn(acc[mi][nt][1] + bv2.y);
                base0[j + 8] = __float2half_rn(acc[mi][nt][2] + bv2.x);
                base1[j + 8] = __float2half_rn(acc[mi][nt][3] + bv2.y);
            }
        }
    }
}

// Output projection: ctx (fp16) @ Wo16^T + bo -> fp32 out.
__global__ __launch_bounds__(256, 2)
void gemm_out_kernel(const __half* __restrict__ A,
                     const __half* __restrict__ W,
                     const float* __restrict__ bias,
                     float* __restrict__ C)
{
    __shared__ uint4 sA[3][512];
    __shared__ uint4 sB[3][512];

    const int bn = blockIdx.x * 128;
    const int bm = blockIdx.y * 128;

    float acc[2][8][4];
    gemm_core_async(A, W, sA, sB, acc, bm, bn);

    const int lane = threadIdx.x & 31;
    const int wid  = threadIdx.x >> 5;
    const int g    = lane >> 2;
    const int t    = lane & 3;
    const int wm   = wid & 3;
    const int wn   = wid >> 2;

#pragma unroll
    for (int mi = 0; mi < 2; mi++) {
        const int row0 = bm + wm * 32 + mi * 16 + g;
#pragma unroll
        for (int nt = 0; nt < 8; nt++) {
            const int col = bn + wn * 64 + nt * 8 + 2 * t;
            const float2 bv2 = *(const float2*)(bias + col);
            float2 o0, o1;
            o0.x = acc[mi][nt][0] + bv2.x; o0.y = acc[mi][nt][1] + bv2.y;
            o1.x = acc[mi][nt][2] + bv2.x; o1.y = acc[mi][nt][3] + bv2.y;
            *(float2*)(C + (size_t)row0 * GN + col)       = o0;
            *(float2*)(C + (size_t)(row0 + 8) * GN + col) = o1;
        }
    }
}

// ---------------------------------------------------------------------------
// fp16 flash attention (unchanged from R13).
// ---------------------------------------------------------------------------
__global__ __launch_bounds__(256, 2)
void attn_f16_kernel(const __half* __restrict__ Q,
                     const __half* __restrict__ Kg,
                     const __half* __restrict__ VT,
                     const float* __restrict__ mask,
                     __half* __restrict__ ctx)
{
    __shared__ uint4 KP[512];
    __shared__ uint4 VP[512];
    __shared__ float msk[64];

    const int tid  = threadIdx.x;
    const int lane = tid & 31;
    const int wid  = tid >> 5;
    const int g    = lane >> 2;
    const int t    = lane & 3;
    const int bh   = blockIdx.y;
    const int b    = bh >> 4;
    const int h    = bh & 15;
    const int q0   = blockIdx.x * 128;
    const int wq   = wid * 16;

    const float SC = 0.125f * LOG2E;

    uint32_t qf[4][4];
    {
        const __half* Qb = Q + (size_t)(b * SEQ + q0 + wq + g) * HDIM + h * 64 + 2 * t;
#pragma unroll
        for (int ks = 0; ks < 4; ks++) {
            qf[ks][0] = *(const uint32_t*)(Qb + 16 * ks);
            qf[ks][1] = *(const uint32_t*)(Qb + 8 * HDIM + 16 * ks);
            qf[ks][2] = *(const uint32_t*)(Qb + 16 * ks + 8);
            qf[ks][3] = *(const uint32_t*)(Qb + 8 * HDIM + 16 * ks + 8);
        }
    }

    const __half* kPtr[2];
    const __half* vPtr[2];
#pragma unroll
    for (int i = 0; i < 2; i++) {
        const int s   = tid + 256 * i;
        const int st  = s & 3;
        const int sg  = (s >> 2) & 7;
        const int ksp = (s >> 5) & 1;
        const int blk = s >> 6;
        kPtr[i] = Kg + (size_t)(b * SEQ + 8 * blk + sg) * HDIM
                     + h * 64 + 32 * ksp + 2 * st;
        vPtr[i] = VT + (size_t)(b * 1024 + h * 64 + 8 * blk + sg) * 2048
                     + 32 * ksp + 2 * st;
    }

    float oacc[8][4];
#pragma unroll
    for (int nt = 0; nt < 8; nt++)
#pragma unroll
        for (int x = 0; x < 4; x++) oacc[nt][x] = 0.0f;
    float lsum0 = 0.0f, lsum1 = 0.0f;

    for (int k0 = 0; k0 < SEQ; k0 += 64) {
#pragma unroll
        for (int i = 0; i < 2; i++) {
            const __half* p = kPtr[i];
            KP[tid + 256 * i] = make_uint4(*(const uint32_t*)(p),
                                           *(const uint32_t*)(p + 8),
                                           *(const uint32_t*)(p + 16),
                                           *(const uint32_t*)(p + 24));
            const __half* q = vPtr[i];
            VP[tid + 256 * i] = make_uint4(*(const uint32_t*)(q),
                                           *(const uint32_t*)(q + 8),
                                           *(const uint32_t*)(q + 16),
                                           *(const uint32_t*)(q + 24));
            kPtr[i] += 64 * HDIM;
            vPtr[i] += 64;
        }
        if (tid < 64) msk[tid] = mask[(size_t)b * SEQ + k0 + tid] * LOG2E;
        __syncthreads();

        float sacc[8][4];
#pragma unroll
        for (int nt = 0; nt < 8; nt++)
#pragma unroll
            for (int x = 0; x < 4; x++) sacc[nt][x] = 0.0f;

#pragma unroll
        for (int nt = 0; nt < 8; nt++) {
#pragma unroll
            for (int ksp = 0; ksp < 2; ksp++) {
                uint4 bF = KP[((nt * 2 + ksp) * 8 + g) * 4 + t];
                mma_f16(sacc[nt], qf[2*ksp][0], qf[2*ksp][1], qf[2*ksp][2], qf[2*ksp][3],
                        bF.x, bF.y);
                mma_f16(sacc[nt], qf[2*ksp+1][0], qf[2*ksp+1][1], qf[2*ksp+1][2], qf[2*ksp+1][3],
                        bF.z, bF.w);
            }
        }

#pragma unroll
        for (int nt = 0; nt < 8; nt++) {
            float2 mk = *(const float2*)&msk[nt * 8 + 2 * t];
            float e0 = ex2(fmaf(sacc[nt][0], SC, mk.x));
            float e1 = ex2(fmaf(sacc[nt][1], SC, mk.y));
            float e2 = ex2(fmaf(sacc[nt][2], SC, mk.x));
            float e3 = ex2(fmaf(sacc[nt][3], SC, mk.y));
            lsum0 += e0 + e1;
            lsum1 += e2 + e3;
            sacc[nt][0] = e0; sacc[nt][1] = e1;
            sacc[nt][2] = e2; sacc[nt][3] = e3;
        }

        uint32_t pf[4][4];
#pragma unroll
        for (int ks = 0; ks < 4; ks++) {
            pf[ks][0] = packh2(sacc[2*ks][0],   sacc[2*ks][1]);
            pf[ks][1] = packh2(sacc[2*ks][2],   sacc[2*ks][3]);
            pf[ks][2] = packh2(sacc[2*ks+1][0], sacc[2*ks+1][1]);
            pf[ks][3] = packh2(sacc[2*ks+1][2], sacc[2*ks+1][3]);
        }

#pragma unroll
        for (int dt = 0; dt < 8; dt++) {
#pragma unroll
            for (int ksp = 0; ksp < 2; ksp++) {
                uint4 bF = VP[((dt * 2 + ksp) * 8 + g) * 4 + t];
                mma_f16(oacc[dt], pf[2*ksp][0], pf[2*ksp][1], pf[2*ksp][2], pf[2*ksp][3],
                        bF.x, bF.y);
                mma_f16(oacc[dt], pf[2*ksp+1][0], pf[2*ksp+1][1], pf[2*ksp+1][2], pf[2*ksp+1][3],
                        bF.z, bF.w);
            }
        }
        __syncthreads();
    }

    lsum0 += __shfl_xor_sync(0xffffffffu, lsum0, 1);
    lsum0 += __shfl_xor_sync(0xffffffffu, lsum0, 2);
    lsum1 += __shfl_xor_sync(0xffffffffu, lsum1, 1);
    lsum1 += __shfl_xor_sync(0xffffffffu, lsum1, 2);
    const float inv0 = 1.0f / lsum0;
    const float inv1 = 1.0f / lsum1;

    __half* c0 = ctx + (size_t)(b * SEQ + q0 + wq + g) * HDIM + h * 64 + 2 * t;
#pragma unroll
    for (int dt = 0; dt < 8; dt++) {
        *(uint32_t*)(c0 + 8 * dt) =
            packh2(oacc[dt][0] * inv0, oacc[dt][1] * inv0);
        *(uint32_t*)(c0 + 8 * HDIM + 8 * dt) =
            packh2(oacc[dt][2] * inv1, oacc[dt][3] * inv1);
    }
}

// ---------------------------------------------------------------------------
// Launch
// ---------------------------------------------------------------------------
extern "C" void kernel_launch(void* const* d_in, const int* in_sizes, int n_in,
                              void* d_out, int out_size)
{
    const float* hs   = (const float*)d_in[0];
    const float* mask = (const float*)d_in[1];
    const float* Wq   = (const float*)d_in[2];
    const float* bq   = (const float*)d_in[3];
    const float* Wk   = (const float*)d_in[4];
    const float* bk   = (const float*)d_in[5];
    const float* Wv   = (const float*)d_in[6];
    const float* bv   = (const float*)d_in[7];
    const float* Wo   = (const float*)d_in[8];
    const float* bo   = (const float*)d_in[9];
    float* out = (float*)d_out;

    __half *qp, *kp, *vp, *cp, *hsp, *wp;
    cudaGetSymbolAddress((void**)&qp, g_q);
    cudaGetSymbolAddress((void**)&kp, g_k);
    cudaGetSymbolAddress((void**)&vp, g_v);
    cudaGetSymbolAddress((void**)&cp, g_ctx);
    cudaGetSymbolAddress((void**)&hsp, g_hs);
    cudaGetSymbolAddress((void**)&wp, g_w);

    cvt_all<<<1024, 256>>>(hs, Wq, Wk, Wv, Wo, hsp, wp);

    qkv_kernel<<<dim3(24, 32), dim3(256)>>>(hsp, wp, bq, bk, bv, qp, kp, vp);

    attn_f16_kernel<<<dim3(SEQ / 128, BATCH * NHEAD), dim3(256)>>>(
        qp, kp, vp, mask, cp);

    gemm_out_kernel<<<dim3(8, 32), dim3(256)>>>(
        cp, wp + 3 * (size_t)GK * GN, bo, out);
}